// round 5
// baseline (speedup 1.0000x reference)
#include <cuda_runtime.h>
#include <cstdint>

#define NNODES 100000
#define EDGES  1600000
#define IN_F   165
#define HID    128

// Scratch (allocation-free rule: __device__ globals)
__device__ float g_bufG[(size_t)NNODES * HID];   // (x@W)*dinv
__device__ float g_bufH[(size_t)NNODES * HID];   // layer-1 activation
__device__ int   g_deg[NNODES];
__device__ float g_dinv[NNODES];
__device__ int   g_rowptr[NNODES + 1];
__device__ int   g_cnt[NNODES];
__device__ int   g_csr_src[EDGES];
__device__ int   g_blockSums[128];

// ---------------- degree ----------------

__global__ void zero2_int_kernel(int* __restrict__ a, int* __restrict__ b, int n) {
    int i = blockIdx.x * blockDim.x + threadIdx.x;
    if (i < n) { a[i] = 0; b[i] = 0; }
}

__global__ void deg_kernel(const int* __restrict__ dst, int* __restrict__ deg, int e) {
    int i = blockIdx.x * blockDim.x + threadIdx.x;
    if (i < e) atomicAdd(&deg[dst[i]], 1);
}

// ---------------- exclusive prefix scan of deg -> rowptr; also dinv ----------------

__global__ __launch_bounds__(256)
void scan_block_sums(const int* __restrict__ deg, int* __restrict__ blockSums, int n) {
    __shared__ int sdata[256];
    int base = blockIdx.x * 2048;
    int tid = threadIdx.x;
    int s = 0;
#pragma unroll
    for (int j = 0; j < 8; j++) {
        int i = base + tid * 8 + j;
        if (i < n) s += deg[i];
    }
    sdata[tid] = s;
    __syncthreads();
    for (int off = 128; off; off >>= 1) {
        if (tid < off) sdata[tid] += sdata[tid + off];
        __syncthreads();
    }
    if (tid == 0) blockSums[blockIdx.x] = sdata[0];
}

__global__ void scan_offsets(int* __restrict__ blockSums, int nb) {
    if (threadIdx.x == 0 && blockIdx.x == 0) {
        int run = 0;
        for (int i = 0; i < nb; i++) { int v = blockSums[i]; blockSums[i] = run; run += v; }
    }
}

__global__ __launch_bounds__(256)
void scan_final(const int* __restrict__ deg, const int* __restrict__ blockSums,
                int* __restrict__ rowptr, float* __restrict__ dinv, int n) {
    __shared__ int tsum[256];
    int base = blockIdx.x * 2048;
    int tid = threadIdx.x;
    int loc[8];
    int dv[8];
    int s = 0;
#pragma unroll
    for (int j = 0; j < 8; j++) {
        int i = base + tid * 8 + j;
        int v = (i < n) ? deg[i] : 0;
        dv[j]  = v;
        loc[j] = s;
        s += v;
    }
    tsum[tid] = s;
    __syncthreads();
    for (int off = 1; off < 256; off <<= 1) {
        int t = (tid >= off) ? tsum[tid - off] : 0;
        __syncthreads();
        tsum[tid] += t;
        __syncthreads();
    }
    int threadOff = tsum[tid] - s;  // exclusive within block
    int cOff = blockSums[blockIdx.x];
#pragma unroll
    for (int j = 0; j < 8; j++) {
        int i = base + tid * 8 + j;
        if (i < n) {
            int rp = cOff + threadOff + loc[j];
            rowptr[i] = rp;
            dinv[i]   = rsqrtf((float)(dv[j] + 1));   // +1 self-loop
            if (i == n - 1) rowptr[n] = rp + dv[j];
        }
    }
}

// ---------------- scatter edges into CSR slots ----------------

__global__ void scatter_kernel(const int* __restrict__ src, const int* __restrict__ dst,
                               const int* __restrict__ rowptr, int* __restrict__ cnt,
                               int* __restrict__ csr, int e) {
    int i = blockIdx.x * blockDim.x + threadIdx.x;
    if (i < e) {
        int d = dst[i];
        int pos = rowptr[d] + atomicAdd(&cnt[d], 1);
        csr[pos] = src[i];
    }
}

// ---------------- tf32 helpers ----------------

__device__ __forceinline__ void split_tf32(float v, float& hi, float& lo) {
    uint32_t h;
    asm("cvt.rna.tf32.f32 %0, %1;" : "=r"(h) : "f"(v));
    float hf = __uint_as_float(h);
    float r = v - hf;                     // exact residual
    uint32_t l;
    asm("cvt.rna.tf32.f32 %0, %1;" : "=r"(l) : "f"(r));
    hi = hf;
    lo = __uint_as_float(l);
}

__device__ __forceinline__ void mma_tf32(float* d,
                                         uint32_t a0, uint32_t a1, uint32_t a2, uint32_t a3,
                                         uint32_t b0, uint32_t b1) {
    asm volatile(
        "mma.sync.aligned.m16n8k8.row.col.f32.tf32.tf32.f32 "
        "{%0,%1,%2,%3}, {%4,%5,%6,%7}, {%8,%9}, {%0,%1,%2,%3};"
        : "+f"(d[0]), "+f"(d[1]), "+f"(d[2]), "+f"(d[3])
        : "r"(a0), "r"(a1), "r"(a2), "r"(a3), "r"(b0), "r"(b1));
}

// ---------------- GEMM (tensor, 3xtf32): G[n,128] = (A[n,K] @ W[K,128]) * dinv[row] -----
// 128x128 tile, BK=16, 256 threads = 8 warps (2x4), each warp 64x32 (4x4 m16n8k8 frags).
// A,W split into tf32 hi/lo in smem; D = Ah*Wh + Al*Wh + Ah*Wl (error ~2^-22).

template <int K>
__global__ __launch_bounds__(256)
void gemm_tf32_kernel(const float* __restrict__ A, const float* __restrict__ W,
                      const float* __restrict__ dinv, float* __restrict__ G, int n) {
    constexpr int BM = 128, BN = 128, BK = 16;
    constexpr int LDA = 136;   // padded row stride: conflict-free fragment LDS
    constexpr int LDB = 136;
    constexpr int TILES = (K + BK - 1) / BK;

    __shared__ float Ah[BK][LDA], Al[BK][LDA];
    __shared__ float Bh[BK][LDB], Bl[BK][LDB];

    const int tid  = threadIdx.x;
    const int wid  = tid >> 5;
    const int lane = tid & 31;
    const int g    = lane >> 2;   // group id 0..7
    const int tig  = lane & 3;    // thread in group 0..3
    const int wm   = wid & 1;     // 0..1 (64 rows each)
    const int wn   = wid >> 1;    // 0..3 (32 cols each)
    const int rowBase = blockIdx.x * BM;

    float acc[4][4][4];
#pragma unroll
    for (int mf = 0; mf < 4; mf++)
#pragma unroll
        for (int nf = 0; nf < 4; nf++)
#pragma unroll
            for (int q = 0; q < 4; q++) acc[mf][nf][q] = 0.f;

    for (int t = 0; t < TILES; t++) {
        const int k0 = t * BK;

        // ---- load A tile [BM][BK] -> Ah/Al[kk][m] (transpose in smem) ----
#pragma unroll
        for (int j = 0; j < 8; j++) {
            int l  = tid + 256 * j;
            int m  = l >> 4;
            int kk = l & 15;
            int gr = rowBase + m;
            int gk = k0 + kk;
            float v = 0.f;
            if (gr < n && gk < K) v = A[(size_t)gr * K + gk];
            float hi, lo;
            split_tf32(v, hi, lo);
            Ah[kk][m] = hi;
            Al[kk][m] = lo;
        }
        // ---- load W tile [BK][BN] -> Bh/Bl[kk][n] (vectorized) ----
#pragma unroll
        for (int j = 0; j < 2; j++) {
            int l4 = tid * 2 + j;          // 512 float4
            int kk = l4 >> 5;
            int n4 = l4 & 31;
            int gk = k0 + kk;
            float4 v = make_float4(0.f, 0.f, 0.f, 0.f);
            if (gk < K) v = *(const float4*)&W[(size_t)gk * BN + n4 * 4];
            float4 hi, lo;
            split_tf32(v.x, hi.x, lo.x);
            split_tf32(v.y, hi.y, lo.y);
            split_tf32(v.z, hi.z, lo.z);
            split_tf32(v.w, hi.w, lo.w);
            *(float4*)&Bh[kk][n4 * 4] = hi;
            *(float4*)&Bl[kk][n4 * 4] = lo;
        }
        __syncthreads();

        // ---- compute: two k8 steps ----
#pragma unroll
        for (int kh = 0; kh < 2; kh++) {
            const int k8 = kh * 8;
            // B fragments (reused across all mf)
            uint32_t bh[4][2], bl[4][2];
#pragma unroll
            for (int nf = 0; nf < 4; nf++) {
                int c = wn * 32 + nf * 8 + g;
                bh[nf][0] = __float_as_uint(Bh[k8 + tig][c]);
                bh[nf][1] = __float_as_uint(Bh[k8 + tig + 4][c]);
                bl[nf][0] = __float_as_uint(Bl[k8 + tig][c]);
                bl[nf][1] = __float_as_uint(Bl[k8 + tig + 4][c]);
            }
#pragma unroll
            for (int mf = 0; mf < 4; mf++) {
                int r = wm * 64 + mf * 16 + g;
                uint32_t ah0 = __float_as_uint(Ah[k8 + tig][r]);
                uint32_t ah1 = __float_as_uint(Ah[k8 + tig][r + 8]);
                uint32_t ah2 = __float_as_uint(Ah[k8 + tig + 4][r]);
                uint32_t ah3 = __float_as_uint(Ah[k8 + tig + 4][r + 8]);
                uint32_t al0 = __float_as_uint(Al[k8 + tig][r]);
                uint32_t al1 = __float_as_uint(Al[k8 + tig][r + 8]);
                uint32_t al2 = __float_as_uint(Al[k8 + tig + 4][r]);
                uint32_t al3 = __float_as_uint(Al[k8 + tig + 4][r + 8]);
#pragma unroll
                for (int nf = 0; nf < 4; nf++) {
                    mma_tf32(acc[mf][nf], ah0, ah1, ah2, ah3, bh[nf][0], bh[nf][1]);
                    mma_tf32(acc[mf][nf], al0, al1, al2, al3, bh[nf][0], bh[nf][1]);
                    mma_tf32(acc[mf][nf], ah0, ah1, ah2, ah3, bl[nf][0], bl[nf][1]);
                }
            }
        }
        __syncthreads();
    }

    // ---- epilogue: scale by dinv, store ----
#pragma unroll
    for (int mf = 0; mf < 4; mf++) {
        int r0 = rowBase + wm * 64 + mf * 16 + g;
        int r1 = r0 + 8;
        float s0 = (r0 < n) ? dinv[r0] : 0.f;
        float s1 = (r1 < n) ? dinv[r1] : 0.f;
#pragma unroll
        for (int nf = 0; nf < 4; nf++) {
            int c = wn * 32 + nf * 8 + tig * 2;
            if (r0 < n) {
                float2 o = make_float2(acc[mf][nf][0] * s0, acc[mf][nf][1] * s0);
                *(float2*)&G[(size_t)r0 * BN + c] = o;
            }
            if (r1 < n) {
                float2 o = make_float2(acc[mf][nf][2] * s1, acc[mf][nf][3] * s1);
                *(float2*)&G[(size_t)r1 * BN + c] = o;
            }
        }
    }
}

// ---------------- fused aggregation: warp per node, CSR segment, no atomics --------
// acc = g[self] + sum_{src in seg} g[src];
//   FINAL=false: h = relu(dinv*acc + b) -> H
//   FINAL=true : h = relu(dinv*acc + b); out = h @ Wc + bc  (warp reduce)

template <bool FINAL>
__global__ __launch_bounds__(256)
void agg_fused_kernel(const float4* __restrict__ g, const int* __restrict__ csr,
                      const int* __restrict__ rowptr,
                      const float* __restrict__ dinv, const float4* __restrict__ bias,
                      float4* __restrict__ h,
                      const float4* __restrict__ Wc4, const float* __restrict__ bc,
                      float2* __restrict__ out, int n) {
    int node = (blockIdx.x * blockDim.x + threadIdx.x) >> 5;
    int lane = threadIdx.x & 31;
    if (node >= n) return;

    const int start = rowptr[node];
    const int end   = rowptr[node + 1];
    const int cnt   = end - start;

    float4 a[8];
    a[0] = g[(size_t)node * 32 + lane];  // self-loop term
#pragma unroll
    for (int i = 1; i < 8; i++) a[i] = make_float4(0.f, 0.f, 0.f, 0.f);

    int j = 0;
    for (; j + 8 <= cnt; j += 8) {
        int idx[8];
#pragma unroll
        for (int u = 0; u < 8; u++) idx[u] = __ldg(&csr[start + j + u]);
#pragma unroll
        for (int u = 0; u < 8; u++) {
            float4 v = g[(size_t)idx[u] * 32 + lane];
            a[u].x += v.x; a[u].y += v.y; a[u].z += v.z; a[u].w += v.w;
        }
    }
    if (j + 4 <= cnt) {
        int idx[4];
#pragma unroll
        for (int u = 0; u < 4; u++) idx[u] = __ldg(&csr[start + j + u]);
#pragma unroll
        for (int u = 0; u < 4; u++) {
            float4 v = g[(size_t)idx[u] * 32 + lane];
            a[u].x += v.x; a[u].y += v.y; a[u].z += v.z; a[u].w += v.w;
        }
        j += 4;
    }
    for (; j < cnt; j++) {
        int s0 = __ldg(&csr[start + j]);
        float4 v = g[(size_t)s0 * 32 + lane];
        a[0].x += v.x; a[0].y += v.y; a[0].z += v.z; a[0].w += v.w;
    }

    float4 acc;
    acc.x = ((a[0].x + a[1].x) + (a[2].x + a[3].x)) + ((a[4].x + a[5].x) + (a[6].x + a[7].x));
    acc.y = ((a[0].y + a[1].y) + (a[2].y + a[3].y)) + ((a[4].y + a[5].y) + (a[6].y + a[7].y));
    acc.z = ((a[0].z + a[1].z) + (a[2].z + a[3].z)) + ((a[4].z + a[5].z) + (a[6].z + a[7].z));
    acc.w = ((a[0].w + a[1].w) + (a[2].w + a[3].w)) + ((a[4].w + a[5].w) + (a[6].w + a[7].w));

    float s = dinv[node];
    float4 bv = bias[lane];
    float4 hv;
    hv.x = fmaxf(fmaf(s, acc.x, bv.x), 0.f);
    hv.y = fmaxf(fmaf(s, acc.y, bv.y), 0.f);
    hv.z = fmaxf(fmaf(s, acc.z, bv.z), 0.f);
    hv.w = fmaxf(fmaf(s, acc.w, bv.w), 0.f);

    if (!FINAL) {
        h[(size_t)node * 32 + lane] = hv;
    } else {
        float4 w0 = __ldg(&Wc4[lane * 2]);
        float4 w1 = __ldg(&Wc4[lane * 2 + 1]);
        float p0 = hv.x * w0.x + hv.y * w0.z + hv.z * w1.x + hv.w * w1.z;
        float p1 = hv.x * w0.y + hv.y * w0.w + hv.z * w1.y + hv.w * w1.w;
#pragma unroll
        for (int off = 16; off; off >>= 1) {
            p0 += __shfl_xor_sync(0xFFFFFFFFu, p0, off);
            p1 += __shfl_xor_sync(0xFFFFFFFFu, p1, off);
        }
        if (lane == 0) out[node] = make_float2(p0 + bc[0], p1 + bc[1]);
    }
}

// ---------------- launch ----------------

extern "C" void kernel_launch(void* const* d_in, const int* in_sizes, int n_in,
                              void* d_out, int out_size) {
    const float* x  = (const float*)d_in[0];
    const int*   ei = (const int*)d_in[1];
    const float* W1 = (const float*)d_in[2];
    const float* b1 = (const float*)d_in[3];
    const float* W2 = (const float*)d_in[4];
    const float* b2 = (const float*)d_in[5];
    const float* Wc = (const float*)d_in[6];
    const float* bc = (const float*)d_in[7];
    float* out = (float*)d_out;

    const int n = NNODES;
    const int e = in_sizes[1] / 2;
    const int* src = ei;
    const int* dst = ei + e;

    float *G, *H, *DINV;
    int *DEG, *ROWPTR, *CNT, *CSR, *BSUMS;
    cudaGetSymbolAddress((void**)&G,      g_bufG);
    cudaGetSymbolAddress((void**)&H,      g_bufH);
    cudaGetSymbolAddress((void**)&DINV,   g_dinv);
    cudaGetSymbolAddress((void**)&DEG,    g_deg);
    cudaGetSymbolAddress((void**)&ROWPTR, g_rowptr);
    cudaGetSymbolAddress((void**)&CNT,    g_cnt);
    cudaGetSymbolAddress((void**)&CSR,    g_csr_src);
    cudaGetSymbolAddress((void**)&BSUMS,  g_blockSums);

    const int gemmB = (n + 127) / 128;
    const int aggB  = (int)(((long long)n * 32 + 255) / 256);
    const int scanB = (n + 2047) / 2048;

    // ---- graph preprocessing ----
    zero2_int_kernel<<<(n + 255) / 256, 256>>>(DEG, CNT, n);
    deg_kernel<<<(e + 255) / 256, 256>>>(dst, DEG, e);
    scan_block_sums<<<scanB, 256>>>(DEG, BSUMS, n);
    scan_offsets<<<1, 32>>>(BSUMS, scanB);
    scan_final<<<scanB, 256>>>(DEG, BSUMS, ROWPTR, DINV, n);
    scatter_kernel<<<(e + 255) / 256, 256>>>(src, dst, ROWPTR, CNT, CSR, e);

    // ---- layer 1 ----
    gemm_tf32_kernel<IN_F><<<gemmB, 256>>>(x, W1, DINV, G, n);
    agg_fused_kernel<false><<<aggB, 256>>>((const float4*)G, CSR, ROWPTR, DINV,
                                           (const float4*)b1, (float4*)H,
                                           nullptr, nullptr, nullptr, n);

    // ---- layer 2 (+ fused classifier) ----
    gemm_tf32_kernel<HID><<<gemmB, 256>>>(H, W2, DINV, G, n);
    agg_fused_kernel<true><<<aggB, 256>>>((const float4*)G, CSR, ROWPTR, DINV,
                                          (const float4*)b2, nullptr,
                                          (const float4*)Wc, bc, (float2*)out, n);
}